// round 7
// baseline (speedup 1.0000x reference)
#include <cuda_runtime.h>
#include <cuda_fp16.h>
#include <mma.h>
#include <cstdint>

using namespace nvcuda;

#define BB 64
#define SS 512
#define II 1024
#define HH 1024
#define GG 4096            // 4*H
#define KW 2048            // I + H
#define NCTA 128
#define SPLIT_SC 2048.0f
#define INV_SC  (1.0f/2048.0f)

// ---------------- static device scratch ----------------
__device__ float  g_xw[(size_t)SS * BB * GG];    // [s][b][g] pre-activations (fp32)
__device__ __half g_x_hi[(size_t)BB * SS * II];
__device__ __half g_x_lo[(size_t)BB * SS * II];
__device__ __half g_w_hi[(size_t)GG * KW];
__device__ __half g_w_lo[(size_t)GG * KW];
__device__ __half g_h_hi[2][BB * HH];
__device__ __half g_h_lo[2][BB * HH];
__device__ unsigned g_chk[8 * 32];               // per-chunk counters, 128B apart

// ---------------- fast activations (error ~1e-6, budget-safe) --------------
__device__ __forceinline__ float fsigmoid(float x) {
    return __fdividef(1.f, 1.f + __expf(-x));
}
__device__ __forceinline__ float ftanh(float x) {
    return 1.f - __fdividef(2.f, __expf(2.f * x) + 1.f);
}

// ---------------- pre-pass: fp16x2 split of x and W, reset state -----------
__global__ void split_init_kernel(const float* __restrict__ x,
                                  const float* __restrict__ W) {
    size_t tid = (size_t)blockIdx.x * blockDim.x + threadIdx.x;
    size_t stride = (size_t)gridDim.x * blockDim.x;
    const size_t nx = (size_t)BB * SS * II;
    const size_t nw = (size_t)GG * KW;
    for (size_t i = tid; i < nx; i += stride) {
        float v = x[i];
        __half h = __float2half_rn(v);
        g_x_hi[i] = h;
        g_x_lo[i] = __float2half_rn((v - __half2float(h)) * SPLIT_SC);
    }
    for (size_t i = tid; i < nw; i += stride) {
        float v = W[i];
        __half h = __float2half_rn(v);
        g_w_hi[i] = h;
        g_w_lo[i] = __float2half_rn((v - __half2float(h)) * SPLIT_SC);
    }
    const __half z = __float2half_rn(0.f);
    for (size_t i = tid; i < (size_t)BB * HH; i += stride) {
        g_h_hi[0][i] = z;
        g_h_lo[0][i] = z;
    }
    for (size_t i = tid; i < 8 * 32; i += stride) g_chk[i] = 0u;
}

// ---------------- Phase A: xW = x @ Wx^T + b  (fp16x2, cp.async 2-stage) ---
// CTA tile 128(M) x 64(N), 8 warps (4x2), warp tile 32x32, K-chunk 32.
// Stage (halves): As_hi[128*40] As_lo[128*40] Bs_hi[64*40] Bs_lo[64*40] = 15360.
#define STG 15360
__global__ void __launch_bounds__(256) gemm_xw_kernel(const float* __restrict__ bias)
{
    extern __shared__ char smraw[];
    half* sb = (half*)smraw;
    float* Cs = (float*)smraw;           // epilogue reuse: [128][68]

    const int m0 = blockIdx.y * 128;
    const int n0 = blockIdx.x * 64;
    const int tid = threadIdx.x;
    const int w = tid >> 5;
    const int wm = (w & 3) * 32;
    const int wn = (w >> 2) * 32;

    const uint32_t smem_u32 = (uint32_t)__cvta_generic_to_shared(sb);

    wmma::fragment<wmma::accumulator, 16, 16, 16, float> acc1[2][2], acc2[2][2];
    #pragma unroll
    for (int i = 0; i < 2; i++)
        #pragma unroll
        for (int j = 0; j < 2; j++) {
            wmma::fill_fragment(acc1[i][j], 0.f);
            wmma::fill_fragment(acc2[i][j], 0.f);
        }

    // async-load one K-chunk into stage s (3 x 16B cp.async per thread + B pair)
    #define PA_LOAD_STAGE(S, K0) { \
        uint32_t st = smem_u32 + (S) * STG * 2; \
        _Pragma("unroll") \
        for (int u = 0; u < 2; u++) { \
            int i = tid + u * 256; \
            int m = i >> 2, q = i & 3; \
            size_t src = (size_t)(m0 + m) * II + (K0) + q * 8; \
            uint32_t d = st + (uint32_t)(m * 40 + q * 8) * 2; \
            asm volatile("cp.async.cg.shared.global [%0], [%1], 16;" :: "r"(d), "l"(&g_x_hi[src])); \
            asm volatile("cp.async.cg.shared.global [%0], [%1], 16;" :: "r"(d + 128*40*2), "l"(&g_x_lo[src])); \
        } \
        { int n = tid >> 2, q = tid & 3; \
          size_t src = (size_t)(n0 + n) * KW + (K0) + q * 8; \
          uint32_t d = st + (uint32_t)(256*40 + n * 40 + q * 8) * 2; \
          asm volatile("cp.async.cg.shared.global [%0], [%1], 16;" :: "r"(d), "l"(&g_w_hi[src])); \
          asm volatile("cp.async.cg.shared.global [%0], [%1], 16;" :: "r"(d + 64*40*2), "l"(&g_w_lo[src])); } \
        asm volatile("cp.async.commit_group;"); }

    PA_LOAD_STAGE(0, 0);

    for (int it = 0; it < 32; it++) {
        if (it < 31) {
            PA_LOAD_STAGE((it + 1) & 1, (it + 1) * 32);
            asm volatile("cp.async.wait_group 1;");
        } else {
            asm volatile("cp.async.wait_group 0;");
        }
        __syncthreads();

        const half* As_hi = sb + (it & 1) * STG;
        const half* As_lo = As_hi + 128 * 40;
        const half* Bs_hi = As_hi + 256 * 40;
        const half* Bs_lo = Bs_hi + 64 * 40;

        #pragma unroll
        for (int kc = 0; kc < 32; kc += 16) {
            wmma::fragment<wmma::matrix_a, 16, 16, 16, half, wmma::row_major> ahi[2], alo[2];
            wmma::fragment<wmma::matrix_b, 16, 16, 16, half, wmma::col_major> bhi[2], blo[2];
            #pragma unroll
            for (int i = 0; i < 2; i++) {
                wmma::load_matrix_sync(ahi[i], &As_hi[(wm + i * 16) * 40 + kc], 40);
                wmma::load_matrix_sync(alo[i], &As_lo[(wm + i * 16) * 40 + kc], 40);
            }
            #pragma unroll
            for (int j = 0; j < 2; j++) {
                wmma::load_matrix_sync(bhi[j], &Bs_hi[(wn + j * 16) * 40 + kc], 40);
                wmma::load_matrix_sync(blo[j], &Bs_lo[(wn + j * 16) * 40 + kc], 40);
            }
            #pragma unroll
            for (int i = 0; i < 2; i++)
                #pragma unroll
                for (int j = 0; j < 2; j++) {
                    wmma::mma_sync(acc1[i][j], ahi[i], bhi[j], acc1[i][j]);
                    wmma::mma_sync(acc2[i][j], ahi[i], blo[j], acc2[i][j]);
                    wmma::mma_sync(acc2[i][j], alo[i], bhi[j], acc2[i][j]);
                }
        }
        __syncthreads();
    }
    #undef PA_LOAD_STAGE

    #pragma unroll
    for (int i = 0; i < 2; i++)
        #pragma unroll
        for (int j = 0; j < 2; j++) {
            #pragma unroll
            for (int e = 0; e < acc1[i][j].num_elements; e++)
                acc1[i][j].x[e] += acc2[i][j].x[e] * INV_SC;
            wmma::store_matrix_sync(&Cs[(wm + i * 16) * 68 + wn + j * 16],
                                    acc1[i][j], 68, wmma::mem_row_major);
        }
    __syncthreads();

    // write out + bias; row m -> (b = m/512, s = m%512); store [s][b][g]
    for (int i = tid; i < 128 * 64; i += 256) {
        int m = i >> 6, n = i & 63;
        int gm = m0 + m;
        int s = gm & 511, b = gm >> 9;
        g_xw[((size_t)s * BB + b) * GG + n0 + n] = Cs[m * 68 + n] + bias[n0 + n];
    }
}

// ---------------- fine-grained chunk wait (lane-0 poll, padded counters) ---
__device__ __forceinline__ void wait_chunk(int c, unsigned target) {
    if ((threadIdx.x & 31) == 0) {
        const unsigned* p = &g_chk[c * 32];
        unsigned v;
        do {
            asm volatile("ld.acquire.gpu.u32 %0, [%1];" : "=r"(v) : "l"(p) : "memory");
            if (v >= target) break;
            __nanosleep(20);
        } while (true);
    }
    __syncwarp();
}

// ---------------- Phase B: persistent recurrent scan (fp16x2) --------------
// CTA owns 8 h-units: gate rows {j0+jj, 1024+j0+jj, 2048+j0+jj, 3072+j0+jj}.
// Wh slice (32 rows x 1024, hi+lo) persistent in SMEM all 512 steps.
__global__ void __launch_bounds__(256, 1) lstm_rec_kernel(float* __restrict__ out)
{
    extern __shared__ char smraw[];
    half* whs_hi = (half*)smraw;                 // [32][1032]
    half* whs_lo = whs_hi + 32 * 1032;           // [32][1032]
    half* hs_hi0 = whs_lo + 32 * 1032;           // [64][136] double-buffered
    half* hs_hi1 = hs_hi0 + 64 * 136;
    half* hs_lo0 = hs_hi1 + 64 * 136;
    half* hs_lo1 = hs_lo0 + 64 * 136;
    float* pres  = (float*)(hs_lo1 + 64 * 136);  // [64][36]
    float* cs    = pres + 64 * 36;               // [512]
    half* hs_hi[2] = { hs_hi0, hs_hi1 };
    half* hs_lo[2] = { hs_lo0, hs_lo1 };

    const int tid = threadIdx.x;
    const int w = tid >> 5;
    const int j0 = blockIdx.x * 8;
    const int my_chunk = j0 >> 7;
    const int wm = (w & 3) * 16;   // batch tile
    const int wn = (w >> 2) * 16;  // gate tile

    // persistent Wh slice: row n -> gate g = (n/8)*1024 + j0 + (n%8)
    for (int i = tid; i < 4096; i += 256) {
        int n = i >> 7, q = i & 127;
        int g = ((n >> 3) << 10) + j0 + (n & 7);
        size_t src = (size_t)g * KW + II + q * 8;
        *(uint4*)&whs_hi[n * 1032 + q * 8] = *(const uint4*)&g_w_hi[src];
        *(uint4*)&whs_lo[n * 1032 + q * 8] = *(const uint4*)&g_w_lo[src];
    }
    for (int i = tid; i < 512; i += 256) cs[i] = 0.f;
    __syncthreads();

    for (int t = 0; t < SS; t++) {
        const half* hbh = g_h_hi[t & 1];
        const half* hbl = g_h_lo[t & 1];
        const unsigned tgt = (unsigned)t * 16u;

        // Prefetch this step's gate pre-activations (h-independent, hides DRAM)
        const float* xwrow = &g_xw[(size_t)t * BB * GG];
        float xpre[2][4];
        #pragma unroll
        for (int u = 0; u < 2; u++) {
            int i = tid + u * 256;
            int b = i >> 3, jj = i & 7;
            const float* xb = xwrow + (size_t)b * GG + j0 + jj;
            xpre[u][0] = __ldcs(xb);
            xpre[u][1] = __ldcs(xb + 1024);
            xpre[u][2] = __ldcs(xb + 2048);
            xpre[u][3] = __ldcs(xb + 3072);
        }

        uint4 rh[4], rl[4];
        #define LOAD_CHUNK(K0) { \
            _Pragma("unroll") \
            for (int u = 0; u < 4; u++) { \
                int idx = tid + u * 256; \
                int b = idx >> 4, q = idx & 15; \
                rh[u] = __ldcg((const uint4*)&hbh[b * HH + (K0) + q * 8]); \
                rl[u] = __ldcg((const uint4*)&hbl[b * HH + (K0) + q * 8]); \
            } }
        #define STORE_CHUNK(BUF) { \
            _Pragma("unroll") \
            for (int u = 0; u < 4; u++) { \
                int idx = tid + u * 256; \
                int b = idx >> 4, q = idx & 15; \
                *(uint4*)&hs_hi[BUF][b * 136 + q * 8] = rh[u]; \
                *(uint4*)&hs_lo[BUF][b * 136 + q * 8] = rl[u]; \
            } }

        wmma::fragment<wmma::accumulator, 16, 16, 16, float> acc1, acc2;
        wmma::fill_fragment(acc1, 0.f);
        wmma::fill_fragment(acc2, 0.f);

        if (t > 0) wait_chunk(0, tgt);
        LOAD_CHUNK(0);
        STORE_CHUNK(0);
        __syncthreads();

        for (int c = 0; c < 8; c++) {
            if (c < 7) {
                if (t > 0) wait_chunk(c + 1, tgt);
                LOAD_CHUNK((c + 1) * 128);
            }
            const int buf = c & 1;
            #pragma unroll
            for (int kc = 0; kc < 128; kc += 16) {
                wmma::fragment<wmma::matrix_a, 16, 16, 16, half, wmma::row_major> ahi, alo;
                wmma::fragment<wmma::matrix_b, 16, 16, 16, half, wmma::col_major> bhi, blo;
                wmma::load_matrix_sync(ahi, &hs_hi[buf][wm * 136 + kc], 136);
                wmma::load_matrix_sync(alo, &hs_lo[buf][wm * 136 + kc], 136);
                wmma::load_matrix_sync(bhi, &whs_hi[wn * 1032 + c * 128 + kc], 1032);
                wmma::load_matrix_sync(blo, &whs_lo[wn * 1032 + c * 128 + kc], 1032);
                wmma::mma_sync(acc1, ahi, bhi, acc1);
                wmma::mma_sync(acc2, ahi, blo, acc2);
                wmma::mma_sync(acc2, alo, bhi, acc2);
            }
            if (c < 7) {
                STORE_CHUNK((c + 1) & 1);
                __syncthreads();
            }
        }
        #undef LOAD_CHUNK
        #undef STORE_CHUNK

        #pragma unroll
        for (int e = 0; e < acc1.num_elements; e++)
            acc1.x[e] += acc2.x[e] * INV_SC;
        wmma::store_matrix_sync(&pres[wm * 36 + wn], acc1, 36, wmma::mem_row_major);
        __syncthreads();

        // gates + state update + outputs
        half* hwh = g_h_hi[(t + 1) & 1];
        half* hwl = g_h_lo[(t + 1) & 1];
        #pragma unroll
        for (int u = 0; u < 2; u++) {
            int i = tid + u * 256;
            int b = i >> 3, jj = i & 7;
            float pc = pres[b * 36 + jj]      + xpre[u][0];
            float pf = pres[b * 36 + 8 + jj]  + xpre[u][1];
            float pu = pres[b * 36 + 16 + jj] + xpre[u][2];
            float po = pres[b * 36 + 24 + jj] + xpre[u][3];
            float cand = ftanh(pc);
            float f = fsigmoid(pf);
            float uu = fsigmoid(pu);
            float o = fsigmoid(po);
            float cn = uu * cand + f * cs[i];
            cs[i] = cn;
            float hn = o * ftanh(cn);
            __half hh = __float2half_rn(hn);
            hwh[b * HH + j0 + jj] = hh;
            hwl[b * HH + j0 + jj] = __float2half_rn((hn - __half2float(hh)) * SPLIT_SC);
            __stcs(&out[((size_t)b * SS + t) * HH + j0 + jj], hn);
            if (t == SS - 1) {
                size_t base1 = (size_t)BB * SS * HH;
                out[base1 + (size_t)b * HH + j0 + jj] = hn;
                out[base1 + (size_t)BB * HH + (size_t)b * HH + j0 + jj] = cn;
            }
        }

        // publish: this CTA finished step t
        if (t < SS - 1) {
            __syncthreads();
            if (tid == 0) {
                __threadfence();
                atomicAdd(&g_chk[my_chunk * 32], 1u);
            }
        }
    }
}

// ---------------- launch ----------------------------------------------------
extern "C" void kernel_launch(void* const* d_in, const int* in_sizes, int n_in,
                              void* d_out, int out_size) {
    const float* x    = (const float*)d_in[0];   // [64, 512, 1024]
    const float* W    = (const float*)d_in[1];   // [4096, 2048]
    const float* bias = (const float*)d_in[2];   // [4096]
    float* out = (float*)d_out;
    (void)in_sizes; (void)n_in; (void)out_size;

    const int smemA = 2 * STG * (int)sizeof(half);              // 61440 B
    const int smemB = (int)((32 * 1032 * 2 + 64 * 136 * 4) * sizeof(half)
                            + (64 * 36 + 512) * sizeof(float)); // 212992 B

    cudaFuncSetAttribute(gemm_xw_kernel,
                         cudaFuncAttributeMaxDynamicSharedMemorySize, smemA);
    cudaFuncSetAttribute(lstm_rec_kernel,
                         cudaFuncAttributeMaxDynamicSharedMemorySize, smemB);

    split_init_kernel<<<512, 256>>>(x, W);

    dim3 gridA(GG / 64, (BB * SS) / 128);
    gemm_xw_kernel<<<gridA, 256, smemA>>>(bias);

    lstm_rec_kernel<<<NCTA, 256, smemB>>>(out);
}

// round 16
// speedup vs baseline: 1.1525x; 1.1525x over previous
#include <cuda_runtime.h>
#include <cuda_fp16.h>
#include <mma.h>
#include <cstdint>

using namespace nvcuda;

#define BB 64
#define SS 512
#define II 1024
#define HH 1024
#define GG 4096            // 4*H
#define KW 2048            // I + H
#define NCTA 128
#define SPLIT_SC 2048.0f
#define INV_SC  (1.0f/2048.0f)

// ---------------- static device scratch ----------------
__device__ float  g_xw[(size_t)SS * BB * GG];    // [s][b][g] pre-activations (fp32)
__device__ __half g_x_hi[(size_t)BB * SS * II];
__device__ __half g_x_lo[(size_t)BB * SS * II];
__device__ __half g_w_hi[(size_t)GG * KW];
__device__ __half g_w_lo[(size_t)GG * KW];
__device__ __half g_h_hi[2][BB * HH];
__device__ __half g_h_lo[2][BB * HH];
__device__ unsigned g_chk[8 * 32];               // per-chunk counters, 128B apart

// ---------------- fast activations --------------------------------------
__device__ __forceinline__ float fsigmoid(float x) {
    return __fdividef(1.f, 1.f + __expf(-x));
}
__device__ __forceinline__ float ftanh(float x) {
    return 1.f - __fdividef(2.f, __expf(2.f * x) + 1.f);
}

// ---------------- pre-pass: fp16x2 split of x and W, reset state ---------
__global__ void split_init_kernel(const float* __restrict__ x,
                                  const float* __restrict__ W) {
    size_t tid = (size_t)blockIdx.x * blockDim.x + threadIdx.x;
    size_t stride = (size_t)gridDim.x * blockDim.x;
    const size_t nx = (size_t)BB * SS * II;
    const size_t nw = (size_t)GG * KW;
    for (size_t i = tid; i < nx; i += stride) {
        float v = x[i];
        __half h = __float2half_rn(v);
        g_x_hi[i] = h;
        g_x_lo[i] = __float2half_rn((v - __half2float(h)) * SPLIT_SC);
    }
    for (size_t i = tid; i < nw; i += stride) {
        float v = W[i];
        __half h = __float2half_rn(v);
        g_w_hi[i] = h;
        g_w_lo[i] = __float2half_rn((v - __half2float(h)) * SPLIT_SC);
    }
    const __half z = __float2half_rn(0.f);
    for (size_t i = tid; i < (size_t)BB * HH; i += stride) {
        g_h_hi[0][i] = z;
        g_h_lo[0][i] = z;
    }
    for (size_t i = tid; i < 8 * 32; i += stride) g_chk[i] = 0u;
}

// ---------------- Phase A: xW = x @ Wx^T + b  (fp16x2 split, wmma) ---------
// R3 form (known-good): CTA tile 128x64, 8 warps (4x2), warp tile 32x32.
__global__ void __launch_bounds__(256) gemm_xw_kernel(const float* __restrict__ bias)
{
    extern __shared__ char smraw[];
    half* As_hi = (half*)smraw;          // [128][40]
    half* As_lo = As_hi + 128 * 40;
    half* Bs_hi = As_lo + 128 * 40;      // [64][40]
    half* Bs_lo = Bs_hi + 64 * 40;
    float* Cs = (float*)smraw;           // reuse: [128][68]

    const int m0 = blockIdx.y * 128;
    const int n0 = blockIdx.x * 64;
    const int tid = threadIdx.x;
    const int w = tid >> 5;
    const int wm = (w & 3) * 32;
    const int wn = (w >> 2) * 32;

    wmma::fragment<wmma::accumulator, 16, 16, 16, float> acc1[2][2], acc2[2][2];
    #pragma unroll
    for (int i = 0; i < 2; i++)
        #pragma unroll
        for (int j = 0; j < 2; j++) {
            wmma::fill_fragment(acc1[i][j], 0.f);
            wmma::fill_fragment(acc2[i][j], 0.f);
        }

    for (int k0 = 0; k0 < II; k0 += 32) {
        #pragma unroll
        for (int i = tid; i < 512; i += 256) {
            int m = i >> 2, q = i & 3;
            size_t src = (size_t)(m0 + m) * II + k0 + q * 8;
            *(uint4*)&As_hi[m * 40 + q * 8] = *(const uint4*)&g_x_hi[src];
            *(uint4*)&As_lo[m * 40 + q * 8] = *(const uint4*)&g_x_lo[src];
        }
        if (tid < 256) {
            int n = tid >> 2, q = tid & 3;
            size_t src = (size_t)(n0 + n) * KW + k0 + q * 8;
            *(uint4*)&Bs_hi[n * 40 + q * 8] = *(const uint4*)&g_w_hi[src];
            *(uint4*)&Bs_lo[n * 40 + q * 8] = *(const uint4*)&g_w_lo[src];
        }
        __syncthreads();
        #pragma unroll
        for (int kc = 0; kc < 32; kc += 16) {
            wmma::fragment<wmma::matrix_a, 16, 16, 16, half, wmma::row_major> ahi[2], alo[2];
            wmma::fragment<wmma::matrix_b, 16, 16, 16, half, wmma::col_major> bhi[2], blo[2];
            #pragma unroll
            for (int i = 0; i < 2; i++) {
                wmma::load_matrix_sync(ahi[i], &As_hi[(wm + i * 16) * 40 + kc], 40);
                wmma::load_matrix_sync(alo[i], &As_lo[(wm + i * 16) * 40 + kc], 40);
            }
            #pragma unroll
            for (int j = 0; j < 2; j++) {
                wmma::load_matrix_sync(bhi[j], &Bs_hi[(wn + j * 16) * 40 + kc], 40);
                wmma::load_matrix_sync(blo[j], &Bs_lo[(wn + j * 16) * 40 + kc], 40);
            }
            #pragma unroll
            for (int i = 0; i < 2; i++)
                #pragma unroll
                for (int j = 0; j < 2; j++) {
                    wmma::mma_sync(acc1[i][j], ahi[i], bhi[j], acc1[i][j]);
                    wmma::mma_sync(acc2[i][j], ahi[i], blo[j], acc2[i][j]);
                    wmma::mma_sync(acc2[i][j], alo[i], bhi[j], acc2[i][j]);
                }
        }
        __syncthreads();
    }

    #pragma unroll
    for (int i = 0; i < 2; i++)
        #pragma unroll
        for (int j = 0; j < 2; j++) {
            #pragma unroll
            for (int e = 0; e < acc1[i][j].num_elements; e++)
                acc1[i][j].x[e] += acc2[i][j].x[e] * INV_SC;
            wmma::store_matrix_sync(&Cs[(wm + i * 16) * 68 + wn + j * 16],
                                    acc1[i][j], 68, wmma::mem_row_major);
        }
    __syncthreads();

    for (int i = tid; i < 128 * 64; i += 256) {
        int m = i >> 6, n = i & 63;
        int gm = m0 + m;
        int s = gm & 511, b = gm >> 9;
        g_xw[((size_t)s * BB + b) * GG + n0 + n] = Cs[m * 68 + n] + bias[n0 + n];
    }
}

// ---------------- fine-grained chunk wait (lane-0 poll, padded counters) ---
__device__ __forceinline__ void wait_chunk(int c, unsigned target) {
    if ((threadIdx.x & 31) == 0) {
        const unsigned* p = &g_chk[c * 32];
        unsigned v;
        do {
            asm volatile("ld.acquire.gpu.u32 %0, [%1];" : "=r"(v) : "l"(p) : "memory");
            if (v >= target) break;
            __nanosleep(20);
        } while (true);
    }
    __syncwarp();
}

// ---------------- Phase B: persistent recurrent scan ----------------------
// CTA owns 8 h-units (32 gate rows). Wh slice persistent in SMEM.
// 32x32 warp tiles with interleaved-k split (mi = w&1 batch half,
// ki = w>>1 takes k16-iters {ki, ki+4} of each 128-chunk), cp.async staging,
// end-of-step 4-way k-reduction through smem. red stride = 36 floats (144B,
// 16B-multiple as wmma requires).
__global__ void __launch_bounds__(256, 1) lstm_rec_kernel(float* __restrict__ out)
{
    extern __shared__ char smraw[];
    half* whs_hi = (half*)smraw;                 // [32][1032]
    half* whs_lo = whs_hi + 32 * 1032;           // [32][1032]
    half* hb_hi0 = whs_lo + 32 * 1032;           // [64][136] double-buffered
    half* hb_hi1 = hb_hi0 + 64 * 136;
    half* hb_lo0 = hb_hi1 + 64 * 136;
    half* hb_lo1 = hb_lo0 + 64 * 136;
    float* pres  = (float*)(hb_lo1 + 64 * 136);  // [64][36]
    float* cs    = pres + 64 * 36;               // [512]
    float* red   = (float*)hb_hi0;               // overlay: 8 x [32][36] partials
    half* hb_hi[2] = { hb_hi0, hb_hi1 };
    half* hb_lo[2] = { hb_lo0, hb_lo1 };

    const int tid = threadIdx.x;
    const int w = tid >> 5;
    const int j0 = blockIdx.x * 8;
    const int my_chunk = j0 >> 7;
    const int mi = w & 1;          // batch half (rows mi*32 .. mi*32+31)
    const int ki = w >> 1;         // k16-iter subset {ki, ki+4} per chunk

    // persistent Wh slice: row n -> gate g = (n/8)*1024 + j0 + (n%8)
    for (int i = tid; i < 4096; i += 256) {
        int n = i >> 7, q = i & 127;
        int g = ((n >> 3) << 10) + j0 + (n & 7);
        size_t src = (size_t)g * KW + II + q * 8;
        *(uint4*)&whs_hi[n * 1032 + q * 8] = *(const uint4*)&g_w_hi[src];
        *(uint4*)&whs_lo[n * 1032 + q * 8] = *(const uint4*)&g_w_lo[src];
    }
    for (int i = tid; i < 512; i += 256) cs[i] = 0.f;
    __syncthreads();

    for (int t = 0; t < SS; t++) {
        const half* hbh = g_h_hi[t & 1];
        const half* hbl = g_h_lo[t & 1];
        const unsigned tgt = (unsigned)t * 16u;

        // prefetch this step's gate pre-activations (h-independent)
        const float* xwrow = &g_xw[(size_t)t * BB * GG];
        float xpre[2][4];
        #pragma unroll
        for (int u = 0; u < 2; u++) {
            int i = tid + u * 256;
            int b = i >> 3, jj = i & 7;
            const float* xb = xwrow + (size_t)b * GG + j0 + jj;
            xpre[u][0] = __ldcs(xb);
            xpre[u][1] = __ldcs(xb + 1024);
            xpre[u][2] = __ldcs(xb + 2048);
            xpre[u][3] = __ldcs(xb + 3072);
        }

        // cp.async stage one FULL 128-chunk (hi+lo, 16KB each) into buffer BUF
        // 64 rows x 16 x 16B granules per array = 1024 granules.
        #define ISSUE_CHUNK(BUF, K0) { \
            uint32_t dhi = (uint32_t)__cvta_generic_to_shared(hb_hi[BUF]); \
            uint32_t dlo = (uint32_t)__cvta_generic_to_shared(hb_lo[BUF]); \
            _Pragma("unroll") \
            for (int u = 0; u < 4; u++) { \
                int idx = tid + u * 256; \
                int b = idx >> 4, q = idx & 15; \
                uint32_t doff = (uint32_t)(b * 136 + q * 8) * 2; \
                const __half* sh = &hbh[b * HH + (K0) + q * 8]; \
                const __half* sl = &hbl[b * HH + (K0) + q * 8]; \
                asm volatile("cp.async.cg.shared.global [%0], [%1], 16;" :: "r"(dhi + doff), "l"(sh)); \
                asm volatile("cp.async.cg.shared.global [%0], [%1], 16;" :: "r"(dlo + doff), "l"(sl)); \
            } \
            asm volatile("cp.async.commit_group;"); }

        wmma::fragment<wmma::accumulator, 16, 16, 16, float> acc1[2][2], acc2[2][2];
        #pragma unroll
        for (int i = 0; i < 2; i++)
            #pragma unroll
            for (int j = 0; j < 2; j++) {
                wmma::fill_fragment(acc1[i][j], 0.f);
                wmma::fill_fragment(acc2[i][j], 0.f);
            }

        if (t > 0) wait_chunk(0, tgt);
        ISSUE_CHUNK(0, 0);

        for (int c = 0; c < 8; c++) {
            asm volatile("cp.async.wait_group 0;");
            __syncthreads();   // buf(c) ready; all warps done with buf((c-1)&1)
            if (c < 7) {
                if (t > 0) wait_chunk(c + 1, tgt);
                ISSUE_CHUNK((c + 1) & 1, (c + 1) * 128);
            }
            const int buf = c & 1;
            const half* Hhi = hb_hi[buf];
            const half* Hlo = hb_lo[buf];
            #pragma unroll
            for (int qq = 0; qq < 2; qq++) {
                const int kc = (ki + qq * 4) * 16;       // within chunk
                const int kw = c * 128 + kc;             // within K=1024
                wmma::fragment<wmma::matrix_a, 16, 16, 16, half, wmma::row_major> ahi[2], alo[2];
                wmma::fragment<wmma::matrix_b, 16, 16, 16, half, wmma::col_major> bhi[2], blo[2];
                #pragma unroll
                for (int i = 0; i < 2; i++) {
                    wmma::load_matrix_sync(ahi[i], &Hhi[(mi * 32 + i * 16) * 136 + kc], 136);
                    wmma::load_matrix_sync(alo[i], &Hlo[(mi * 32 + i * 16) * 136 + kc], 136);
                }
                #pragma unroll
                for (int j = 0; j < 2; j++) {
                    wmma::load_matrix_sync(bhi[j], &whs_hi[(j * 16) * 1032 + kw], 1032);
                    wmma::load_matrix_sync(blo[j], &whs_lo[(j * 16) * 1032 + kw], 1032);
                }
                #pragma unroll
                for (int i = 0; i < 2; i++)
                    #pragma unroll
                    for (int j = 0; j < 2; j++) {
                        wmma::mma_sync(acc1[i][j], ahi[i], bhi[j], acc1[i][j]);
                        wmma::mma_sync(acc2[i][j], ahi[i], blo[j], acc2[i][j]);
                        wmma::mma_sync(acc2[i][j], alo[i], bhi[j], acc2[i][j]);
                    }
            }
        }
        #undef ISSUE_CHUNK

        __syncthreads();   // all MMA reads of hb buffers done -> red overlay safe

        // combine hi/lo and store 32x36-strided partial tile per warp
        #pragma unroll
        for (int i = 0; i < 2; i++)
            #pragma unroll
            for (int j = 0; j < 2; j++) {
                #pragma unroll
                for (int e = 0; e < acc1[i][j].num_elements; e++)
                    acc1[i][j].x[e] += acc2[i][j].x[e] * INV_SC;
                wmma::store_matrix_sync(&red[w * 1152 + (i * 16) * 36 + j * 16],
                                        acc1[i][j], 36, wmma::mem_row_major);
            }
        __syncthreads();

        // 4-way k-reduction: pres[b][n] = sum_ki red[2*ki + (b>=32)][b%32][n]
        #pragma unroll
        for (int u = 0; u < 8; u++) {
            int oidx = tid + u * 256;
            int b = oidx >> 5, n = oidx & 31;
            int bmi = b >> 5, r = b & 31;
            float s = red[(0 * 2 + bmi) * 1152 + r * 36 + n]
                    + red[(1 * 2 + bmi) * 1152 + r * 36 + n]
                    + red[(2 * 2 + bmi) * 1152 + r * 36 + n]
                    + red[(3 * 2 + bmi) * 1152 + r * 36 + n];
            pres[b * 36 + n] = s;
        }
        __syncthreads();

        // gates + state update + outputs
        half* hwh = g_h_hi[(t + 1) & 1];
        half* hwl = g_h_lo[(t + 1) & 1];
        #pragma unroll
        for (int u = 0; u < 2; u++) {
            int i = tid + u * 256;
            int b = i >> 3, jj = i & 7;
            float pc = pres[b * 36 + jj]      + xpre[u][0];
            float pf = pres[b * 36 + 8 + jj]  + xpre[u][1];
            float pu = pres[b * 36 + 16 + jj] + xpre[u][2];
            float po = pres[b * 36 + 24 + jj] + xpre[u][3];
            float cand = ftanh(pc);
            float f = fsigmoid(pf);
            float uu = fsigmoid(pu);
            float o = fsigmoid(po);
            float cn = uu * cand + f * cs[i];
            cs[i] = cn;
            float hn = o * ftanh(cn);
            __half hh = __float2half_rn(hn);
            hwh[b * HH + j0 + jj] = hh;
            hwl[b * HH + j0 + jj] = __float2half_rn((hn - __half2float(hh)) * SPLIT_SC);
            __stcs(&out[((size_t)b * SS + t) * HH + j0 + jj], hn);
            if (t == SS - 1) {
                size_t base1 = (size_t)BB * SS * HH;
                out[base1 + (size_t)b * HH + j0 + jj] = hn;
                out[base1 + (size_t)BB * HH + (size_t)b * HH + j0 + jj] = cn;
            }
        }

        // publish: this CTA finished step t
        if (t < SS - 1) {
            __syncthreads();
            if (tid == 0) {
                __threadfence();
                atomicAdd(&g_chk[my_chunk * 32], 1u);
            }
        }
    }
}

// ---------------- launch ----------------------------------------------------
extern "C" void kernel_launch(void* const* d_in, const int* in_sizes, int n_in,
                              void* d_out, int out_size) {
    const float* x    = (const float*)d_in[0];   // [64, 512, 1024]
    const float* W    = (const float*)d_in[1];   // [4096, 2048]
    const float* bias = (const float*)d_in[2];   // [4096]
    float* out = (float*)d_out;
    (void)in_sizes; (void)n_in; (void)out_size;

    const int smemA = 128 * 68 * (int)sizeof(float);            // 34816 B
    const int smemB = (int)((32 * 1032 * 2 + 64 * 136 * 4) * sizeof(half)
                            + (64 * 36 + 512) * sizeof(float)); // 212992 B

    cudaFuncSetAttribute(gemm_xw_kernel,
                         cudaFuncAttributeMaxDynamicSharedMemorySize, smemA);
    cudaFuncSetAttribute(lstm_rec_kernel,
                         cudaFuncAttributeMaxDynamicSharedMemorySize, smemB);

    split_init_kernel<<<512, 256>>>(x, W);

    dim3 gridA(GG / 64, (BB * SS) / 128);
    gemm_xw_kernel<<<gridA, 256, smemA>>>(bias);

    lstm_rec_kernel<<<NCTA, 256, smemB>>>(out);
}